// round 3
// baseline (speedup 1.0000x reference)
#include <cuda_runtime.h>
#include <cuda_bf16.h>
#include <cstdint>

// InfoNCE loss, B=8192, D=512 — mma.sync bf16 path (tcgen05 unavailable:
// harness lowers via compute_103 PTX, which rejects tcgen05/.cta_group).
// k1: row norms + bf16 normalized feats
// k2: HMMA bf16 GEMM F·F^T fused with exp((s-1)/T) row partial sums
// k3: per-row reduce + exact fp32 target logit -> nll
// k4: mean

#define BN   8192
#define DK   512
#define NT   64           // 64 x 64 tiles of 128x128
#define KC   64           // K chunk (bf16 elems)
#define INV_T 14.285714285714286f
#define K2E   20.60992915f   // log2(e)/T

// ---- scratch (device globals; no runtime allocation) ----
__device__ uint4  g_feats4[BN * DK / 8];   // bf16 normalized feats, 8 MB
__device__ float  g_invn[BN];
__device__ float  g_partial[NT * BN];      // per (col-tile, row) partial sums, 2 MB
__device__ float  g_nll[BN];

// ---- helpers ----
__device__ __forceinline__ uint32_t smem_u32(const void* p) {
    uint32_t a;
    asm("{ .reg .u64 t; cvta.to.shared.u64 t, %1; cvt.u32.u64 %0, t; }" : "=r"(a) : "l"(p));
    return a;
}

__device__ __forceinline__ void cp16(uint32_t saddr, const void* g) {
    asm volatile("cp.async.cg.shared.global [%0], [%1], 16;"
                 :: "r"(saddr), "l"(g) : "memory");
}

__device__ __forceinline__ void ldsm_x4(uint32_t* r, uint32_t addr) {
    asm volatile("ldmatrix.sync.aligned.m8n8.x4.shared.b16 {%0,%1,%2,%3}, [%4];"
                 : "=r"(r[0]), "=r"(r[1]), "=r"(r[2]), "=r"(r[3]) : "r"(addr));
}

__device__ __forceinline__ void mma16816(float* c, const uint32_t* a, const uint32_t* b) {
    asm volatile("mma.sync.aligned.m16n8k16.row.col.f32.bf16.bf16.f32 "
                 "{%0,%1,%2,%3}, {%4,%5,%6,%7}, {%8,%9}, {%0,%1,%2,%3};"
                 : "+f"(c[0]), "+f"(c[1]), "+f"(c[2]), "+f"(c[3])
                 : "r"(a[0]), "r"(a[1]), "r"(a[2]), "r"(a[3]), "r"(b[0]), "r"(b[1]));
}

// ------------------------------------------------------------------
// k1: norms + bf16 feats
// ------------------------------------------------------------------
__global__ __launch_bounds__(256) void k1_norm(const float* __restrict__ x) {
    int gw = (blockIdx.x * blockDim.x + threadIdx.x) >> 5;
    int lane = threadIdx.x & 31;
    if (gw >= BN) return;
    const float* xr = x + gw * DK;
    float v[16];
    float ss = 0.f;
#pragma unroll
    for (int k = 0; k < 16; k++) {
        v[k] = xr[lane + 32 * k];
        ss = fmaf(v[k], v[k], ss);
    }
#pragma unroll
    for (int o = 16; o > 0; o >>= 1)
        ss += __shfl_xor_sync(0xFFFFFFFFu, ss, o);
    float inv = 1.0f / fmaxf(sqrtf(ss), 1e-12f);
    __nv_bfloat16* out = ((__nv_bfloat16*)g_feats4) + gw * DK;
#pragma unroll
    for (int k = 0; k < 16; k++)
        out[lane + 32 * k] = __float2bfloat16(v[k] * inv);
    if (lane == 0) g_invn[gw] = inv;
}

// ------------------------------------------------------------------
// k2: 128x128 tile GEMM via mma.sync bf16, double-buffered cp.async,
//     fused exp epilogue with per-row partial sums (no atomics).
// smem layout (dynamic, 66560 B):
//   [0      , 32768) : A buffers  [2][128][64] bf16  (swizzled 128B rows)
//   [32768  , 65536) : B buffers  [2][128][64] bf16
//   [65536  , 66560) : rowsum     [2][128] float
// ------------------------------------------------------------------
__global__ __launch_bounds__(256, 2) void k2_gemm() {
    extern __shared__ char smem[];
    const uint32_t sbase = smem_u32(smem);
    float* rs = (float*)(smem + 65536);

    const int tid = threadIdx.x, wid = tid >> 5, lane = tid & 31;
    const int wr = wid >> 1;          // warp row group 0..3  (m 32*wr)
    const int wc = wid & 1;           // warp col group 0..1  (n 64*wc)
    const int bi = blockIdx.y, bj = blockIdx.x;
    const int ra = bi * 128, rb = bj * 128;

    float acc[2][8][4];
#pragma unroll
    for (int mf = 0; mf < 2; mf++)
#pragma unroll
        for (int nf = 0; nf < 8; nf++)
#pragma unroll
            for (int e = 0; e < 4; e++) acc[mf][nf][e] = 0.f;

    // ---- cp.async chunk loader: 4 vectors A + 4 vectors B per thread ----
    auto issue = [&](int kc, int buf) {
        const uint32_t ab = sbase + buf * 16384;
        const uint32_t bb = sbase + 32768 + buf * 16384;
#pragma unroll
        for (int t = 0; t < 4; t++) {
            int idx = tid + t * 256;          // 0..1023
            int row = idx >> 3, kv = idx & 7; // 8 x 16B vectors per row
            uint32_t sb = (uint32_t)(row * 128 + ((kv * 16) ^ ((row & 7) << 4)));
            cp16(ab + sb, &g_feats4[(ra + row) * 64 + kc * 8 + kv]);
            cp16(bb + sb, &g_feats4[(rb + row) * 64 + kc * 8 + kv]);
        }
        asm volatile("cp.async.commit_group;" ::: "memory");
    };

    issue(0, 0);

    // precompute lane-derived ldmatrix address pieces
    // A: m = mbase + (lane&15), kbyte += ((lane>>4)<<4)
    const int a_mo  = lane & 15;
    const int a_kb  = (lane >> 4) << 4;
    // B: n = nbase + ((lane>>4)<<3) + (lane&7), kbyte += (((lane>>3)&1)<<4)
    const int b_no  = ((lane >> 4) << 3) + (lane & 7);
    const int b_kb  = ((lane >> 3) & 1) << 4;

    for (int kc = 0; kc < DK / KC; kc++) {
        if (kc + 1 < DK / KC) issue(kc + 1, (kc + 1) & 1);
        if (kc + 1 < DK / KC)
            asm volatile("cp.async.wait_group 1;" ::: "memory");
        else
            asm volatile("cp.async.wait_group 0;" ::: "memory");
        __syncthreads();

        const uint32_t ab = sbase + (kc & 1) * 16384;
        const uint32_t bb = sbase + 32768 + (kc & 1) * 16384;

#pragma unroll
        for (int ks = 0; ks < 4; ks++) {
            const int k0b = ks * 32;  // k0*2 bytes
            uint32_t afrag[2][4], bfrag[8][2];
#pragma unroll
            for (int mf = 0; mf < 2; mf++) {
                int m = wr * 32 + mf * 16 + a_mo;
                uint32_t addr = ab + m * 128 + (uint32_t)((k0b + a_kb) ^ ((m & 7) << 4));
                ldsm_x4(afrag[mf], addr);
            }
#pragma unroll
            for (int p = 0; p < 4; p++) {   // n-tile pairs
                int n = wc * 64 + p * 16 + b_no;
                uint32_t addr = bb + n * 128 + (uint32_t)((k0b + b_kb) ^ ((n & 7) << 4));
                uint32_t r[4];
                ldsm_x4(r, addr);
                bfrag[2 * p][0] = r[0]; bfrag[2 * p][1] = r[1];
                bfrag[2 * p + 1][0] = r[2]; bfrag[2 * p + 1][1] = r[3];
            }
#pragma unroll
            for (int mf = 0; mf < 2; mf++)
#pragma unroll
                for (int nf = 0; nf < 8; nf++)
                    mma16816(acc[mf][nf], afrag[mf], bfrag[nf]);
        }
        __syncthreads();
    }

    // ---- fused epilogue: exp((s-1)/T), skip diagonal, per-row sums ----
#pragma unroll
    for (int mf = 0; mf < 2; mf++) {
#pragma unroll
        for (int half = 0; half < 2; half++) {
            int m_loc = wr * 32 + mf * 16 + half * 8 + (lane >> 2);
            int gi = ra + m_loc;
            float sum = 0.f;
#pragma unroll
            for (int nf = 0; nf < 8; nf++) {
#pragma unroll
                for (int e = 0; e < 2; e++) {
                    float s = acc[mf][nf][half * 2 + e];
                    int gj = rb + wc * 64 + nf * 8 + ((lane & 3) << 1) + e;
                    float ex;
                    asm("ex2.approx.ftz.f32 %0, %1;" : "=f"(ex)
                        : "f"(fmaf(s, K2E, -K2E)));
                    if (gj != gi) sum += ex;
                }
            }
            sum += __shfl_xor_sync(0xFFFFFFFFu, sum, 1);
            sum += __shfl_xor_sync(0xFFFFFFFFu, sum, 2);
            if ((lane & 3) == 0) rs[wc * 128 + m_loc] = sum;
        }
    }
    __syncthreads();
    if (tid < 128)
        g_partial[bj * BN + ra + tid] = rs[tid] + rs[128 + tid];
}

// ------------------------------------------------------------------
// k3: reduce partials + exact fp32 target logit -> nll per row
// ------------------------------------------------------------------
__global__ __launch_bounds__(256) void k3_row(const float* __restrict__ x,
                                              const int* __restrict__ y) {
    int i = (blockIdx.x * blockDim.x + threadIdx.x) >> 5;
    int lane = threadIdx.x & 31;
    if (i >= BN) return;

    float S = g_partial[lane * BN + i] + g_partial[(lane + 32) * BN + i];

    int yi = y[i];
    int c = yi + (yi >= i ? 1 : 0);
    const float* xi = x + i * DK;
    const float* xc = x + c * DK;
    float d = 0.f;
#pragma unroll
    for (int k = 0; k < 16; k++)
        d = fmaf(xi[lane + 32 * k], xc[lane + 32 * k], d);

#pragma unroll
    for (int o = 16; o > 0; o >>= 1) {
        S += __shfl_xor_sync(0xFFFFFFFFu, S, o);
        d += __shfl_xor_sync(0xFFFFFFFFu, d, o);
    }

    if (lane == 0) {
        float t = d * g_invn[i] * g_invn[c];   // exact cos sim for target
        float lg;
        asm("lg2.approx.f32 %0, %1;" : "=f"(lg) : "f"(S));
        float lnS = lg * 0.6931471805599453f;
        // nll = log(S) + 1/T - t/T    (shift by 1/T restored)
        g_nll[i] = lnS + (1.0f - t) * INV_T;
    }
}

// ------------------------------------------------------------------
// k4: mean over rows
// ------------------------------------------------------------------
__global__ __launch_bounds__(1024) void k4_mean(float* __restrict__ out) {
    __shared__ float sh[1024];
    int tid = threadIdx.x;
    float a = 0.f;
#pragma unroll
    for (int j = 0; j < BN / 1024; j++)
        a += g_nll[tid + j * 1024];
    sh[tid] = a;
    __syncthreads();
#pragma unroll
    for (int o = 512; o > 0; o >>= 1) {
        if (tid < o) sh[tid] += sh[tid + o];
        __syncthreads();
    }
    if (tid == 0) out[0] = sh[0] * (1.0f / (float)BN);
}

// ------------------------------------------------------------------
extern "C" void kernel_launch(void* const* d_in, const int* in_sizes, int n_in,
                              void* d_out, int out_size) {
    const float* x = (const float*)d_in[0];
    const int*   y = (const int*)d_in[1];
    float* out = (float*)d_out;

    cudaFuncSetAttribute(k2_gemm, cudaFuncAttributeMaxDynamicSharedMemorySize, 66560);

    k1_norm<<<BN / 8, 256>>>(x);
    k2_gemm<<<dim3(NT, NT), 256, 66560>>>();
    k3_row<<<BN / 8, 256>>>(x, y);
    k4_mean<<<1, 1024>>>(out);
}

// round 4
// speedup vs baseline: 1.6422x; 1.6422x over previous
#include <cuda_runtime.h>
#include <cuda_bf16.h>
#include <cstdint>

// InfoNCE loss, B=8192, D=512 — symmetric-triangle mma.sync bf16 path.
// sim = F·F^T is symmetric: compute only upper-triangle tiles; off-diagonal
// tiles emit BOTH row sums (for bi-block rows) and column sums (= partials
// for bj-block rows). 2080 tiles instead of 4096.

#define BN   8192
#define DK   512
#define NT   64           // 64 x 64 tiles of 128x128
#define NTRI 2080         // NT*(NT+1)/2
#define KC   64           // K chunk (bf16 elems)
#define INV_T 14.285714285714286f
#define K2E   20.60992915f   // log2(e)/T

// ---- scratch (device globals; no runtime allocation) ----
__device__ uint4  g_feats4[BN * DK / 8];   // bf16 normalized feats, 8 MB
__device__ float  g_invn[BN];
__device__ float  g_partial[NT * BN];      // per (col-tile, row) partial sums, 2 MB
__device__ float  g_nll[BN];

// ---- helpers ----
__device__ __forceinline__ uint32_t smem_u32(const void* p) {
    uint32_t a;
    asm("{ .reg .u64 t; cvta.to.shared.u64 t, %1; cvt.u32.u64 %0, t; }" : "=r"(a) : "l"(p));
    return a;
}

__device__ __forceinline__ void cp16(uint32_t saddr, const void* g) {
    asm volatile("cp.async.cg.shared.global [%0], [%1], 16;"
                 :: "r"(saddr), "l"(g) : "memory");
}

__device__ __forceinline__ void ldsm_x4(uint32_t* r, uint32_t addr) {
    asm volatile("ldmatrix.sync.aligned.m8n8.x4.shared.b16 {%0,%1,%2,%3}, [%4];"
                 : "=r"(r[0]), "=r"(r[1]), "=r"(r[2]), "=r"(r[3]) : "r"(addr));
}

__device__ __forceinline__ void mma16816(float* c, const uint32_t* a, const uint32_t* b) {
    asm volatile("mma.sync.aligned.m16n8k16.row.col.f32.bf16.bf16.f32 "
                 "{%0,%1,%2,%3}, {%4,%5,%6,%7}, {%8,%9}, {%0,%1,%2,%3};"
                 : "+f"(c[0]), "+f"(c[1]), "+f"(c[2]), "+f"(c[3])
                 : "r"(a[0]), "r"(a[1]), "r"(a[2]), "r"(a[3]), "r"(b[0]), "r"(b[1]));
}

// ------------------------------------------------------------------
// k1: norms + bf16 feats
// ------------------------------------------------------------------
__global__ __launch_bounds__(256) void k1_norm(const float* __restrict__ x) {
    int gw = (blockIdx.x * blockDim.x + threadIdx.x) >> 5;
    int lane = threadIdx.x & 31;
    if (gw >= BN) return;
    const float* xr = x + gw * DK;
    float v[16];
    float ss = 0.f;
#pragma unroll
    for (int k = 0; k < 16; k++) {
        v[k] = xr[lane + 32 * k];
        ss = fmaf(v[k], v[k], ss);
    }
#pragma unroll
    for (int o = 16; o > 0; o >>= 1)
        ss += __shfl_xor_sync(0xFFFFFFFFu, ss, o);
    float inv = 1.0f / fmaxf(sqrtf(ss), 1e-12f);
    __nv_bfloat16* out = ((__nv_bfloat16*)g_feats4) + gw * DK;
#pragma unroll
    for (int k = 0; k < 16; k++)
        out[lane + 32 * k] = __float2bfloat16(v[k] * inv);
    if (lane == 0) g_invn[gw] = inv;
}

// ------------------------------------------------------------------
// k2: triangular 128x128 tile GEMM, mma.sync bf16, double-buffered cp.async,
//     fused exp epilogue emitting row sums AND (off-diag) column sums.
// smem (dynamic, 68608 B):
//   [0      , 32768) : A buffers [2][128][64] bf16 (swizzled 128B rows)
//   [32768  , 65536) : B buffers [2][128][64] bf16
//   [65536  , 66560) : rowsum  [2][128] float   (per wc group)
//   [66560  , 68608) : colsum  [4][128] float   (per wr group)
// ------------------------------------------------------------------
__global__ __launch_bounds__(256, 2) void k2_gemm() {
    extern __shared__ char smem[];
    const uint32_t sbase = smem_u32(smem);
    float* rs = (float*)(smem + 65536);
    float* cs = (float*)(smem + 66560);

    const int tid = threadIdx.x, wid = tid >> 5, lane = tid & 31;
    const int wr = wid >> 1;          // warp row group 0..3  (m 32*wr)
    const int wc = wid & 1;           // warp col group 0..1  (n 64*wc)

    // decode triangular tile index: reversed-triangle trick
    int u = NTRI - 1 - (int)blockIdx.x;
    int q = (int)((sqrtf(8.0f * (float)u + 1.0f) - 1.0f) * 0.5f);
    while ((q + 1) * (q + 2) / 2 <= u) q++;
    while (q * (q + 1) / 2 > u) q--;
    const int bi = NT - 1 - q;
    const int bj = NT - 1 - (u - q * (q + 1) / 2);
    const int ra = bi * 128, rb = bj * 128;
    const bool diag = (bi == bj);

    float acc[2][8][4];
#pragma unroll
    for (int mf = 0; mf < 2; mf++)
#pragma unroll
        for (int nf = 0; nf < 8; nf++)
#pragma unroll
            for (int e = 0; e < 4; e++) acc[mf][nf][e] = 0.f;

    // ---- cp.async chunk loader: 4 vectors A + 4 vectors B per thread ----
    auto issue = [&](int kc, int buf) {
        const uint32_t ab = sbase + buf * 16384;
        const uint32_t bb = sbase + 32768 + buf * 16384;
#pragma unroll
        for (int t = 0; t < 4; t++) {
            int idx = tid + t * 256;          // 0..1023
            int row = idx >> 3, kv = idx & 7; // 8 x 16B vectors per row
            uint32_t sb = (uint32_t)(row * 128 + ((kv * 16) ^ ((row & 7) << 4)));
            cp16(ab + sb, &g_feats4[(ra + row) * 64 + kc * 8 + kv]);
            cp16(bb + sb, &g_feats4[(rb + row) * 64 + kc * 8 + kv]);
        }
        asm volatile("cp.async.commit_group;" ::: "memory");
    };

    issue(0, 0);

    // lane-derived ldmatrix address pieces
    const int a_mo = lane & 15;
    const int a_kb = (lane >> 4) << 4;
    const int b_no = ((lane >> 4) << 3) + (lane & 7);
    const int b_kb = ((lane >> 3) & 1) << 4;

    for (int kc = 0; kc < DK / KC; kc++) {
        if (kc + 1 < DK / KC) {
            issue(kc + 1, (kc + 1) & 1);
            asm volatile("cp.async.wait_group 1;" ::: "memory");
        } else {
            asm volatile("cp.async.wait_group 0;" ::: "memory");
        }
        __syncthreads();

        const uint32_t ab = sbase + (kc & 1) * 16384;
        const uint32_t bb = sbase + 32768 + (kc & 1) * 16384;

#pragma unroll
        for (int ks = 0; ks < 4; ks++) {
            const int k0b = ks * 32;
            uint32_t afrag[2][4], bfrag[8][2];
#pragma unroll
            for (int mf = 0; mf < 2; mf++) {
                int m = wr * 32 + mf * 16 + a_mo;
                uint32_t addr = ab + m * 128 + (uint32_t)((k0b + a_kb) ^ ((m & 7) << 4));
                ldsm_x4(afrag[mf], addr);
            }
#pragma unroll
            for (int p = 0; p < 4; p++) {
                int n = wc * 64 + p * 16 + b_no;
                uint32_t addr = bb + n * 128 + (uint32_t)((k0b + b_kb) ^ ((n & 7) << 4));
                uint32_t r[4];
                ldsm_x4(r, addr);
                bfrag[2 * p][0] = r[0]; bfrag[2 * p][1] = r[1];
                bfrag[2 * p + 1][0] = r[2]; bfrag[2 * p + 1][1] = r[3];
            }
#pragma unroll
            for (int mf = 0; mf < 2; mf++)
#pragma unroll
                for (int nf = 0; nf < 8; nf++)
                    mma16816(acc[mf][nf], afrag[mf], bfrag[nf]);
        }
        __syncthreads();
    }

    // ---- fused epilogue: exp((s-1)/T), row sums + column sums ----
    float csum[8][2];
#pragma unroll
    for (int nf = 0; nf < 8; nf++) { csum[nf][0] = 0.f; csum[nf][1] = 0.f; }

#pragma unroll
    for (int mf = 0; mf < 2; mf++) {
#pragma unroll
        for (int half = 0; half < 2; half++) {
            int m_loc = wr * 32 + mf * 16 + half * 8 + (lane >> 2);
            int gi = ra + m_loc;
            float sum = 0.f;
#pragma unroll
            for (int nf = 0; nf < 8; nf++) {
#pragma unroll
                for (int e = 0; e < 2; e++) {
                    float s = acc[mf][nf][half * 2 + e];
                    int gj = rb + wc * 64 + nf * 8 + ((lane & 3) << 1) + e;
                    float ex;
                    asm("ex2.approx.ftz.f32 %0, %1;" : "=f"(ex)
                        : "f"(fmaf(s, K2E, -K2E)));
                    float exk = (gj != gi) ? ex : 0.f;   // diagonal excluded
                    sum += exk;
                    csum[nf][e] += exk;
                }
            }
            sum += __shfl_xor_sync(0xFFFFFFFFu, sum, 1);
            sum += __shfl_xor_sync(0xFFFFFFFFu, sum, 2);
            if ((lane & 3) == 0) rs[wc * 128 + m_loc] = sum;
        }
    }

    // column reduce across the 8 m-positions in this warp (lane-groups)
#pragma unroll
    for (int nf = 0; nf < 8; nf++)
#pragma unroll
        for (int e = 0; e < 2; e++) {
            csum[nf][e] += __shfl_xor_sync(0xFFFFFFFFu, csum[nf][e], 4);
            csum[nf][e] += __shfl_xor_sync(0xFFFFFFFFu, csum[nf][e], 8);
            csum[nf][e] += __shfl_xor_sync(0xFFFFFFFFu, csum[nf][e], 16);
        }
    if (lane < 4) {
#pragma unroll
        for (int nf = 0; nf < 8; nf++)
#pragma unroll
            for (int e = 0; e < 2; e++)
                cs[wr * 128 + wc * 64 + nf * 8 + lane * 2 + e] = csum[nf][e];
    }
    __syncthreads();

    if (tid < 128) {
        g_partial[bj * BN + ra + tid] = rs[tid] + rs[128 + tid];
        if (!diag)
            g_partial[bi * BN + rb + tid] =
                cs[tid] + cs[128 + tid] + cs[256 + tid] + cs[384 + tid];
    }
}

// ------------------------------------------------------------------
// k3: reduce partials + exact fp32 target logit -> nll per row
// ------------------------------------------------------------------
__global__ __launch_bounds__(256) void k3_row(const float* __restrict__ x,
                                              const int* __restrict__ y) {
    int i = (blockIdx.x * blockDim.x + threadIdx.x) >> 5;
    int lane = threadIdx.x & 31;
    if (i >= BN) return;

    float S = g_partial[lane * BN + i] + g_partial[(lane + 32) * BN + i];

    int yi = y[i];
    int c = yi + (yi >= i ? 1 : 0);
    const float* xi = x + i * DK;
    const float* xc = x + c * DK;
    float d = 0.f;
#pragma unroll
    for (int k = 0; k < 16; k++)
        d = fmaf(xi[lane + 32 * k], xc[lane + 32 * k], d);

#pragma unroll
    for (int o = 16; o > 0; o >>= 1) {
        S += __shfl_xor_sync(0xFFFFFFFFu, S, o);
        d += __shfl_xor_sync(0xFFFFFFFFu, d, o);
    }

    if (lane == 0) {
        float t = d * g_invn[i] * g_invn[c];   // exact cos sim for target
        float lg;
        asm("lg2.approx.f32 %0, %1;" : "=f"(lg) : "f"(S));
        float lnS = lg * 0.6931471805599453f;
        g_nll[i] = lnS + (1.0f - t) * INV_T;   // shift by 1/T restored
    }
}

// ------------------------------------------------------------------
// k4: mean over rows
// ------------------------------------------------------------------
__global__ __launch_bounds__(1024) void k4_mean(float* __restrict__ out) {
    __shared__ float sh[1024];
    int tid = threadIdx.x;
    float a = 0.f;
#pragma unroll
    for (int j = 0; j < BN / 1024; j++)
        a += g_nll[tid + j * 1024];
    sh[tid] = a;
    __syncthreads();
#pragma unroll
    for (int o = 512; o > 0; o >>= 1) {
        if (tid < o) sh[tid] += sh[tid + o];
        __syncthreads();
    }
    if (tid == 0) out[0] = sh[0] * (1.0f / (float)BN);
}

// ------------------------------------------------------------------
extern "C" void kernel_launch(void* const* d_in, const int* in_sizes, int n_in,
                              void* d_out, int out_size) {
    const float* x = (const float*)d_in[0];
    const int*   y = (const int*)d_in[1];
    float* out = (float*)d_out;

    cudaFuncSetAttribute(k2_gemm, cudaFuncAttributeMaxDynamicSharedMemorySize, 68608);

    k1_norm<<<BN / 8, 256>>>(x);
    k2_gemm<<<NTRI, 256, 68608>>>();
    k3_row<<<BN / 8, 256>>>(x, y);
    k4_mean<<<1, 1024>>>(out);
}

// round 5
// speedup vs baseline: 1.6550x; 1.0078x over previous
#include <cuda_runtime.h>
#include <cuda_bf16.h>
#include <cstdint>

// InfoNCE loss, B=8192, D=512 — symmetric-triangle mma.sync bf16 path.
// R5: single bar.sync per K-chunk, diag-only predication in epilogue,
//     k3+k4 fused via last-block-done reduction.

#define BN   8192
#define DK   512
#define NT   64           // 64 x 64 tiles of 128x128
#define NTRI 2080         // NT*(NT+1)/2
#define KC   64           // K chunk (bf16 elems)
#define K3B  1024         // k3 blocks
#define INV_T 14.285714285714286f
#define K2E   20.60992915f   // log2(e)/T

// ---- scratch (device globals; no runtime allocation) ----
__device__ uint4  g_feats4[BN * DK / 8];   // bf16 normalized feats, 8 MB
__device__ float  g_invn[BN];
__device__ float  g_partial[NT * BN];      // per (col-tile, row) partial sums
__device__ float  g_blk[K3B];
__device__ unsigned int g_cnt;

// ---- helpers ----
__device__ __forceinline__ uint32_t smem_u32(const void* p) {
    uint32_t a;
    asm("{ .reg .u64 t; cvta.to.shared.u64 t, %1; cvt.u32.u64 %0, t; }" : "=r"(a) : "l"(p));
    return a;
}

__device__ __forceinline__ void cp16(uint32_t saddr, const void* g) {
    asm volatile("cp.async.cg.shared.global [%0], [%1], 16;"
                 :: "r"(saddr), "l"(g) : "memory");
}

__device__ __forceinline__ void ldsm_x4(uint32_t* r, uint32_t addr) {
    asm volatile("ldmatrix.sync.aligned.m8n8.x4.shared.b16 {%0,%1,%2,%3}, [%4];"
                 : "=r"(r[0]), "=r"(r[1]), "=r"(r[2]), "=r"(r[3]) : "r"(addr));
}

__device__ __forceinline__ void mma16816(float* c, const uint32_t* a, const uint32_t* b) {
    asm volatile("mma.sync.aligned.m16n8k16.row.col.f32.bf16.bf16.f32 "
                 "{%0,%1,%2,%3}, {%4,%5,%6,%7}, {%8,%9}, {%0,%1,%2,%3};"
                 : "+f"(c[0]), "+f"(c[1]), "+f"(c[2]), "+f"(c[3])
                 : "r"(a[0]), "r"(a[1]), "r"(a[2]), "r"(a[3]), "r"(b[0]), "r"(b[1]));
}

// ------------------------------------------------------------------
// k1: norms + bf16 feats (+ reset k3 completion counter)
// ------------------------------------------------------------------
__global__ __launch_bounds__(256) void k1_norm(const float* __restrict__ x) {
    if (blockIdx.x == 0 && threadIdx.x == 0) g_cnt = 0;
    int gw = (blockIdx.x * blockDim.x + threadIdx.x) >> 5;
    int lane = threadIdx.x & 31;
    if (gw >= BN) return;
    const float* xr = x + gw * DK;
    float v[16];
    float ss = 0.f;
#pragma unroll
    for (int k = 0; k < 16; k++) {
        v[k] = xr[lane + 32 * k];
        ss = fmaf(v[k], v[k], ss);
    }
#pragma unroll
    for (int o = 16; o > 0; o >>= 1)
        ss += __shfl_xor_sync(0xFFFFFFFFu, ss, o);
    float inv = 1.0f / fmaxf(sqrtf(ss), 1e-12f);
    __nv_bfloat16* out = ((__nv_bfloat16*)g_feats4) + gw * DK;
#pragma unroll
    for (int k = 0; k < 16; k++)
        out[lane + 32 * k] = __float2bfloat16(v[k] * inv);
    if (lane == 0) g_invn[gw] = inv;
}

// ------------------------------------------------------------------
// k2: triangular 128x128 tile GEMM, mma.sync bf16, double-buffered cp.async
//     (one bar.sync per chunk), fused exp epilogue.
// smem (dynamic, 68608 B):
//   [0      , 32768) : A buffers [2][128][64] bf16 (swizzled 128B rows)
//   [32768  , 65536) : B buffers [2][128][64] bf16
//   [65536  , 66560) : rowsum  [2][128] float
//   [66560  , 68608) : colsum  [4][128] float
// ------------------------------------------------------------------
__global__ __launch_bounds__(256, 2) void k2_gemm() {
    extern __shared__ char smem[];
    const uint32_t sbase = smem_u32(smem);
    float* rs = (float*)(smem + 65536);
    float* cs = (float*)(smem + 66560);

    const int tid = threadIdx.x, wid = tid >> 5, lane = tid & 31;
    const int wr = wid >> 1;          // warp row group 0..3  (m 32*wr)
    const int wc = wid & 1;           // warp col group 0..1  (n 64*wc)

    // decode triangular tile index
    int u = NTRI - 1 - (int)blockIdx.x;
    int q = (int)((sqrtf(8.0f * (float)u + 1.0f) - 1.0f) * 0.5f);
    while ((q + 1) * (q + 2) / 2 <= u) q++;
    while (q * (q + 1) / 2 > u) q--;
    const int bi = NT - 1 - q;
    const int bj = NT - 1 - (u - q * (q + 1) / 2);
    const int ra = bi * 128, rb = bj * 128;
    const bool diag = (bi == bj);

    float acc[2][8][4];
#pragma unroll
    for (int mf = 0; mf < 2; mf++)
#pragma unroll
        for (int nf = 0; nf < 8; nf++)
#pragma unroll
            for (int e = 0; e < 4; e++) acc[mf][nf][e] = 0.f;

    auto issue = [&](int kc, int buf) {
        const uint32_t ab = sbase + buf * 16384;
        const uint32_t bb = sbase + 32768 + buf * 16384;
#pragma unroll
        for (int t = 0; t < 4; t++) {
            int idx = tid + t * 256;          // 0..1023
            int row = idx >> 3, kv = idx & 7; // 8 x 16B vectors per row
            uint32_t sb = (uint32_t)(row * 128 + ((kv * 16) ^ ((row & 7) << 4)));
            cp16(ab + sb, &g_feats4[(ra + row) * 64 + kc * 8 + kv]);
            cp16(bb + sb, &g_feats4[(rb + row) * 64 + kc * 8 + kv]);
        }
        asm volatile("cp.async.commit_group;" ::: "memory");
    };

    issue(0, 0);

    const int a_mo = lane & 15;
    const int a_kb = (lane >> 4) << 4;
    const int b_no = ((lane >> 4) << 3) + (lane & 7);
    const int b_kb = ((lane >> 3) & 1) << 4;

    for (int kc = 0; kc < DK / KC; kc++) {
        asm volatile("cp.async.wait_group 0;" ::: "memory");
        __syncthreads();           // buf kc visible to all; all done reading buf kc^1
        if (kc + 1 < DK / KC) issue(kc + 1, (kc + 1) & 1);

        const uint32_t ab = sbase + (kc & 1) * 16384;
        const uint32_t bb = sbase + 32768 + (kc & 1) * 16384;

#pragma unroll
        for (int ks = 0; ks < 4; ks++) {
            const int k0b = ks * 32;
            uint32_t afrag[2][4], bfrag[8][2];
#pragma unroll
            for (int mf = 0; mf < 2; mf++) {
                int m = wr * 32 + mf * 16 + a_mo;
                uint32_t addr = ab + m * 128 + (uint32_t)((k0b + a_kb) ^ ((m & 7) << 4));
                ldsm_x4(afrag[mf], addr);
            }
#pragma unroll
            for (int p = 0; p < 4; p++) {
                int n = wc * 64 + p * 16 + b_no;
                uint32_t addr = bb + n * 128 + (uint32_t)((k0b + b_kb) ^ ((n & 7) << 4));
                uint32_t r[4];
                ldsm_x4(r, addr);
                bfrag[2 * p][0] = r[0]; bfrag[2 * p][1] = r[1];
                bfrag[2 * p + 1][0] = r[2]; bfrag[2 * p + 1][1] = r[3];
            }
#pragma unroll
            for (int mf = 0; mf < 2; mf++)
#pragma unroll
                for (int nf = 0; nf < 8; nf++)
                    mma16816(acc[mf][nf], afrag[mf], bfrag[nf]);
        }
    }
    __syncthreads();   // acc done; smem A/B free, rs/cs about to be written

    // ---- fused epilogue ----
    if (!diag) {
        float csum[8][2];
#pragma unroll
        for (int nf = 0; nf < 8; nf++) { csum[nf][0] = 0.f; csum[nf][1] = 0.f; }
#pragma unroll
        for (int mf = 0; mf < 2; mf++) {
#pragma unroll
            for (int half = 0; half < 2; half++) {
                int m_loc = wr * 32 + mf * 16 + half * 8 + (lane >> 2);
                float sum = 0.f;
#pragma unroll
                for (int nf = 0; nf < 8; nf++) {
#pragma unroll
                    for (int e = 0; e < 2; e++) {
                        float ex;
                        asm("ex2.approx.ftz.f32 %0, %1;" : "=f"(ex)
                            : "f"(fmaf(acc[mf][nf][half * 2 + e], K2E, -K2E)));
                        sum += ex;
                        csum[nf][e] += ex;
                    }
                }
                sum += __shfl_xor_sync(0xFFFFFFFFu, sum, 1);
                sum += __shfl_xor_sync(0xFFFFFFFFu, sum, 2);
                if ((lane & 3) == 0) rs[wc * 128 + m_loc] = sum;
            }
        }
#pragma unroll
        for (int nf = 0; nf < 8; nf++)
#pragma unroll
            for (int e = 0; e < 2; e++) {
                csum[nf][e] += __shfl_xor_sync(0xFFFFFFFFu, csum[nf][e], 4);
                csum[nf][e] += __shfl_xor_sync(0xFFFFFFFFu, csum[nf][e], 8);
                csum[nf][e] += __shfl_xor_sync(0xFFFFFFFFu, csum[nf][e], 16);
            }
        if (lane < 4) {
#pragma unroll
            for (int nf = 0; nf < 8; nf++)
#pragma unroll
                for (int e = 0; e < 2; e++)
                    cs[wr * 128 + wc * 64 + nf * 8 + lane * 2 + e] = csum[nf][e];
        }
        __syncthreads();
        if (tid < 128) {
            g_partial[bj * BN + ra + tid] = rs[tid] + rs[128 + tid];
            g_partial[bi * BN + rb + tid] =
                cs[tid] + cs[128 + tid] + cs[256 + tid] + cs[384 + tid];
        }
    } else {
#pragma unroll
        for (int mf = 0; mf < 2; mf++) {
#pragma unroll
            for (int half = 0; half < 2; half++) {
                int m_loc = wr * 32 + mf * 16 + half * 8 + (lane >> 2);
                int gi = ra + m_loc;
                float sum = 0.f;
#pragma unroll
                for (int nf = 0; nf < 8; nf++) {
#pragma unroll
                    for (int e = 0; e < 2; e++) {
                        int gj = rb + wc * 64 + nf * 8 + ((lane & 3) << 1) + e;
                        float ex;
                        asm("ex2.approx.ftz.f32 %0, %1;" : "=f"(ex)
                            : "f"(fmaf(acc[mf][nf][half * 2 + e], K2E, -K2E)));
                        if (gj != gi) sum += ex;
                    }
                }
                sum += __shfl_xor_sync(0xFFFFFFFFu, sum, 1);
                sum += __shfl_xor_sync(0xFFFFFFFFu, sum, 2);
                if ((lane & 3) == 0) rs[wc * 128 + m_loc] = sum;
            }
        }
        __syncthreads();
        if (tid < 128)
            g_partial[bj * BN + ra + tid] = rs[tid] + rs[128 + tid];
    }
}

// ------------------------------------------------------------------
// k3: partial reduce + exact target logit -> nll; fused final mean via
//     last-block-done (deterministic: fixed-order reduction of g_blk).
// ------------------------------------------------------------------
__global__ __launch_bounds__(256) void k3_row(const float* __restrict__ x,
                                              const int* __restrict__ y,
                                              float* __restrict__ out) {
    __shared__ float s8[8];
    __shared__ float sfin[256];
    __shared__ unsigned int slast;

    int wid = threadIdx.x >> 5, lane = threadIdx.x & 31;
    int i = blockIdx.x * 8 + wid;

    float S = g_partial[lane * BN + i] + g_partial[(lane + 32) * BN + i];

    int yi = y[i];
    int c = yi + (yi >= i ? 1 : 0);
    const float* xi = x + i * DK;
    const float* xc = x + c * DK;
    float d = 0.f;
#pragma unroll
    for (int k = 0; k < 16; k++)
        d = fmaf(xi[lane + 32 * k], xc[lane + 32 * k], d);

#pragma unroll
    for (int o = 16; o > 0; o >>= 1) {
        S += __shfl_xor_sync(0xFFFFFFFFu, S, o);
        d += __shfl_xor_sync(0xFFFFFFFFu, d, o);
    }

    if (lane == 0) {
        float t = d * g_invn[i] * g_invn[c];
        float lg;
        asm("lg2.approx.f32 %0, %1;" : "=f"(lg) : "f"(S));
        s8[wid] = lg * 0.6931471805599453f + (1.0f - t) * INV_T;
    }
    __syncthreads();

    if (threadIdx.x == 0) {
        float b = 0.f;
#pragma unroll
        for (int w = 0; w < 8; w++) b += s8[w];
        g_blk[blockIdx.x] = b;
        __threadfence();
        unsigned int old = atomicAdd(&g_cnt, 1u);
        slast = (old == K3B - 1) ? 1u : 0u;
    }
    __syncthreads();

    if (slast) {
        __threadfence();
        float a = 0.f;
#pragma unroll
        for (int j = 0; j < K3B / 256; j++)
            a += g_blk[threadIdx.x + j * 256];
        sfin[threadIdx.x] = a;
        __syncthreads();
#pragma unroll
        for (int o = 128; o > 0; o >>= 1) {
            if (threadIdx.x < o) sfin[threadIdx.x] += sfin[threadIdx.x + o];
            __syncthreads();
        }
        if (threadIdx.x == 0) out[0] = sfin[0] * (1.0f / (float)BN);
    }
}

// ------------------------------------------------------------------
extern "C" void kernel_launch(void* const* d_in, const int* in_sizes, int n_in,
                              void* d_out, int out_size) {
    const float* x = (const float*)d_in[0];
    const int*   y = (const int*)d_in[1];
    float* out = (float*)d_out;

    cudaFuncSetAttribute(k2_gemm, cudaFuncAttributeMaxDynamicSharedMemorySize, 68608);

    k1_norm<<<BN / 8, 256>>>(x);
    k2_gemm<<<NTRI, 256, 68608>>>();
    k3_row<<<K3B, 256>>>(x, y, out);
}